// round 7
// baseline (speedup 1.0000x reference)
#include <cuda_runtime.h>
#include <cstdint>

// ProcessorNet reduction (exact up to fp reassociation):
//   z_0 = x@wd.T + bd                               [B,16]
//   m'_t = relu(z_t) * prog_t
//   z_{t+1} = z_t + m'_t @ A + c,   A = wu.T@wd.T (STEP-INVARIANT), c = bu@wd.T
//   R = sum_t m'_t ;  out = x + R@wu.T + 64*bu
// TWO rows per thread; z column-packed as 8x f32x2 (fma.rn.f32x2).
// A rows 0..11 stream from __constant__ (LDC port), rows 12..16 (incl. c)
// + prog from shared (LDS port) — both ports stay under the fma floor.

#define HDIM 128
#define LSTEPS 64

struct Consts {
    float Arow[17][16];        // rows 0..15 = A[j][i]; row 16 = c[i]
    float wd2[128][16];        // wd2[h][i] = wd[i][h]
    float prog[LSTEPS][16];
    float wupc[64][16][2];     // wupc[hp][j] = {wu[2hp][j], wu[2hp+1][j]}
    float bd[16];
    float bu64[128];           // 64*bu[h]
};
__device__ Consts g_c;

__constant__ ulonglong2 cA[17][4];   // copy of Arow (1088 B)

// shared layout (floats): tile 256*33=8448 | persist (Arow..bu64) 5536
#define TILE_FLOATS 8448
#define PERSIST_FLOATS 5536
#define SMEM_FLOATS (TILE_FLOATS + PERSIST_FLOATS)   // 13984
#define SMEM_BYTES (SMEM_FLOATS * 4)                 // 55936

__global__ void setup_kernel(const float* __restrict__ prog,
                             const float* __restrict__ wd,
                             const float* __restrict__ bd,
                             const float* __restrict__ wu,
                             const float* __restrict__ bu) {
    int tid = threadIdx.x;  // 256 threads, 1 block
    {   // A[j][i] = sum_h wu[h][j] * wd[i][h]
        int j = tid >> 4, i = tid & 15;
        float s = 0.f;
        #pragma unroll 8
        for (int h = 0; h < HDIM; ++h) s += wu[h * 16 + j] * wd[i * HDIM + h];
        g_c.Arow[j][i] = s;
    }
    if (tid < 16) {
        int i = tid;
        float s = 0.f;
        #pragma unroll 8
        for (int h = 0; h < HDIM; ++h) s += bu[h] * wd[i * HDIM + h];
        g_c.Arow[16][i] = s;   // c row
        g_c.bd[i] = bd[i];
    }
    for (int idx = tid; idx < LSTEPS * 16; idx += 256)
        g_c.prog[idx >> 4][idx & 15] = prog[idx];
    for (int idx = tid; idx < 128 * 16; idx += 256) {
        int h = idx >> 4, i = idx & 15;
        g_c.wd2[h][i] = wd[i * HDIM + h];
    }
    for (int idx = tid; idx < 64 * 16; idx += 256) {
        int hp = idx >> 4, j = idx & 15;
        g_c.wupc[hp][j][0] = wu[(2 * hp) * 16 + j];
        g_c.wupc[hp][j][1] = wu[(2 * hp + 1) * 16 + j];
    }
    for (int idx = tid; idx < 128; idx += 256) g_c.bu64[idx] = 64.f * bu[idx];
}

// ---- packed f32x2 helpers ----
typedef unsigned long long u64;

__device__ __forceinline__ u64 pk(float x, float y) {
    u64 r; asm("mov.b64 %0, {%1, %2};" : "=l"(r) : "f"(x), "f"(y)); return r;
}
__device__ __forceinline__ void upk(u64 v, float& x, float& y) {
    asm("mov.b64 {%0, %1}, %2;" : "=f"(x), "=f"(y) : "l"(v));
}
__device__ __forceinline__ u64 fma2(u64 a, u64 b, u64 c) {
    u64 d; asm("fma.rn.f32x2 %0, %1, %2, %3;" : "=l"(d) : "l"(a), "l"(b), "l"(c)); return d;
}
__device__ __forceinline__ u64 add2(u64 a, u64 b) {
    u64 d; asm("add.rn.f32x2 %0, %1, %2;" : "=l"(d) : "l"(a), "l"(b)); return d;
}

// phase A: z += x_row @ wd.T for one 256-row group
__device__ __forceinline__ void phaseA(const float* __restrict__ xg,
                                       float* tile, const float* s_wd2,
                                       u64 z2[8], int tid) {
    for (int ch = 0; ch < 4; ++ch) {
        __syncthreads();
        for (int f = tid; f < 8192; f += 256) {
            int r = f >> 5, c = f & 31;
            tile[r * 33 + c] = xg[(long)r * HDIM + ch * 32 + c];
        }
        __syncthreads();
        #pragma unroll
        for (int c = 0; c < 32; ++c) {
            float xv = tile[tid * 33 + c];
            u64 xs = pk(xv, xv);
            const ulonglong2* w = (const ulonglong2*)(s_wd2 + (ch * 32 + c) * 16);
            #pragma unroll
            for (int kk = 0; kk < 4; ++kk) {
                ulonglong2 wv = w[kk];
                z2[2 * kk]     = fma2(xs, wv.x, z2[2 * kk]);
                z2[2 * kk + 1] = fma2(xs, wv.y, z2[2 * kk + 1]);
            }
        }
    }
}

// phase C: out_row = x_row + R @ wu.T + 64*bu for one 256-row group
__device__ __forceinline__ void phaseC(const float* __restrict__ xg,
                                       float* __restrict__ og,
                                       float* tile, const float* s_wupc,
                                       const float* s_bu,
                                       const u64 Racc2[8], int tid) {
    u64 Rs[16];
    #pragma unroll
    for (int k = 0; k < 8; ++k) {
        float r0, r1;
        upk(Racc2[k], r0, r1);
        Rs[2 * k]     = pk(r0, r0);
        Rs[2 * k + 1] = pk(r1, r1);
    }
    for (int ch = 0; ch < 4; ++ch) {
        __syncthreads();
        #pragma unroll
        for (int hp = 0; hp < 16; ++hp) {
            int h2 = ch * 16 + hp;
            u64 acc = *(const u64*)(s_bu + h2 * 2);
            const ulonglong2* urow = (const ulonglong2*)(s_wupc + h2 * 32);
            #pragma unroll
            for (int jj = 0; jj < 8; ++jj) {
                ulonglong2 u = urow[jj];
                acc = fma2(Rs[2 * jj],     u.x, acc);
                acc = fma2(Rs[2 * jj + 1], u.y, acc);
            }
            float y0, y1;
            upk(acc, y0, y1);
            tile[tid * 33 + 2 * hp]     = y0;
            tile[tid * 33 + 2 * hp + 1] = y1;
        }
        __syncthreads();
        for (int f = tid; f < 8192; f += 256) {
            int r = f >> 5, c = f & 31;
            long g = (long)r * HDIM + ch * 32 + c;
            og[g] = xg[g] + tile[r * 33 + c];
        }
    }
}

__global__ __launch_bounds__(256, 2)
void proc_kernel(const float* __restrict__ x, float* __restrict__ out) {
    extern __shared__ float sm[];
    float* tile   = sm;                     // 8448
    float* s_A    = sm + TILE_FLOATS;       // 272 (rows 12..16 used)
    float* s_wd2  = s_A + 272;              // 2048
    float* s_prog = s_wd2 + 2048;           // 1024
    float* s_wupc = s_prog + 1024;          // 2048
    float* s_bd   = s_wupc + 2048;          // 16
    float* s_bu   = s_bd + 16;              // 128

    int tid = threadIdx.x;

    // copy persistent consts (Arow..bu64 contiguous in Consts)
    {
        const float4* src = (const float4*)&g_c.Arow[0][0];
        float4* dst = (float4*)s_A;
        for (int i = tid; i < PERSIST_FLOATS / 4; i += 256) dst[i] = src[i];
    }
    __syncthreads();

    long row0 = (long)blockIdx.x * 512;     // 512 rows/block (2 per thread)
    const float* xa = x + row0 * HDIM;
    const float* xb = xa + 256L * HDIM;
    float* oa = out + row0 * HDIM;
    float* ob = oa + 256L * HDIM;

    u64 za[8], zb[8];
    #pragma unroll
    for (int k = 0; k < 8; ++k) {
        u64 b = *(const u64*)(s_bd + 2 * k);
        za[k] = b; zb[k] = b;
    }

    // ---- phase A for both row groups ----
    phaseA(xa, tile, s_wd2, za, tid);
    phaseA(xb, tile, s_wd2, zb, tid);
    __syncthreads();

    // ---- phase B: 64 steps; A operands split LDC (rows 0..11) / LDS ----
    u64 Ra[8], Rb[8];
    #pragma unroll
    for (int k = 0; k < 8; ++k) { Ra[k] = 0ull; Rb[k] = 0ull; }
    const u64 one2 = pk(1.f, 1.f);

    #pragma unroll 1
    for (int t = 0; t < LSTEPS; ++t) {
        // prog for this step (4x LDS.128)
        const float4* prq = (const float4*)(s_prog + t * 16);
        float4 p0 = prq[0], p1 = prq[1], p2 = prq[2], p3 = prq[3];
        float pr[16] = {p0.x, p0.y, p0.z, p0.w, p1.x, p1.y, p1.z, p1.w,
                        p2.x, p2.y, p2.z, p2.w, p3.x, p3.y, p3.z, p3.w};

        // m' = relu(z) * prog
        float ma[16], mb[16];
        #pragma unroll
        for (int k = 0; k < 8; ++k) {
            float u, v;
            upk(za[k], u, v);
            ma[2 * k]     = fmaxf(u, 0.f) * pr[2 * k];
            ma[2 * k + 1] = fmaxf(v, 0.f) * pr[2 * k + 1];
            upk(zb[k], u, v);
            mb[2 * k]     = fmaxf(u, 0.f) * pr[2 * k];
            mb[2 * k + 1] = fmaxf(v, 0.f) * pr[2 * k + 1];
        }
        // R += m'
        #pragma unroll
        for (int k = 0; k < 8; ++k) {
            Ra[k] = add2(Ra[k], pk(ma[2 * k], ma[2 * k + 1]));
            Rb[k] = add2(Rb[k], pk(mb[2 * k], mb[2 * k + 1]));
        }
        // z += m' @ A + c  (row 16 of A is c, multiplier 1.0)
        #pragma unroll
        for (int j = 0; j < 17; ++j) {
            u64 mja = (j < 16) ? pk(ma[j], ma[j]) : one2;
            u64 mjb = (j < 16) ? pk(mb[j], mb[j]) : one2;
            ulonglong2 r0, r1;
            if (j < 12) {            // constant port (t-invariant, hoistable)
                r0 = cA[j][0]; r1 = cA[j][1];
            } else {                  // shared port
                const ulonglong2* arow = (const ulonglong2*)(s_A + j * 16);
                r0 = arow[0]; r1 = arow[1];
            }
            za[0] = fma2(mja, r0.x, za[0]);  za[1] = fma2(mja, r0.y, za[1]);
            zb[0] = fma2(mjb, r0.x, zb[0]);  zb[1] = fma2(mjb, r0.y, zb[1]);
            za[2] = fma2(mja, r1.x, za[2]);  za[3] = fma2(mja, r1.y, za[3]);
            zb[2] = fma2(mjb, r1.x, zb[2]);  zb[3] = fma2(mjb, r1.y, zb[3]);
            ulonglong2 r2, r3;
            if (j < 12) {
                r2 = cA[j][2]; r3 = cA[j][3];
            } else {
                const ulonglong2* arow = (const ulonglong2*)(s_A + j * 16);
                r2 = arow[2]; r3 = arow[3];
            }
            za[4] = fma2(mja, r2.x, za[4]);  za[5] = fma2(mja, r2.y, za[5]);
            zb[4] = fma2(mjb, r2.x, zb[4]);  zb[5] = fma2(mjb, r2.y, zb[5]);
            za[6] = fma2(mja, r3.x, za[6]);  za[7] = fma2(mja, r3.y, za[7]);
            zb[6] = fma2(mjb, r3.x, zb[6]);  zb[7] = fma2(mjb, r3.y, zb[7]);
        }
    }

    // ---- phase C for both row groups ----
    phaseC(xa, oa, tile, s_wupc, s_bu, Ra, tid);
    phaseC(xb, ob, tile, s_wupc, s_bu, Rb, tid);
}

extern "C" void kernel_launch(void* const* d_in, const int* in_sizes, int n_in,
                              void* d_out, int out_size) {
    const float* x    = (const float*)d_in[0];
    const float* prog = (const float*)d_in[1];
    const float* wd   = (const float*)d_in[2];
    const float* bd   = (const float*)d_in[3];
    const float* wu   = (const float*)d_in[4];
    const float* bu   = (const float*)d_in[5];
    float* out = (float*)d_out;

    cudaFuncSetAttribute(proc_kernel,
                         cudaFuncAttributeMaxDynamicSharedMemorySize, SMEM_BYTES);

    setup_kernel<<<1, 256>>>(prog, wd, bd, wu, bu);

    // copy A (17x16 floats, Arow is at offset 0 of g_c) into constant memory
    void* gc_ptr = nullptr;
    cudaGetSymbolAddress(&gc_ptr, g_c);
    cudaMemcpyToSymbolAsync(cA, gc_ptr, 17 * 16 * sizeof(float), 0,
                            cudaMemcpyDeviceToDevice);

    int rows = in_sizes[0] / HDIM;          // 262144
    int blocks = rows / 512;                // 512
    proc_kernel<<<blocks, 256, SMEM_BYTES>>>(x, out);
}

// round 8
// speedup vs baseline: 1.0044x; 1.0044x over previous
#include <cuda_runtime.h>
#include <cstdint>

// ProcessorNet reduction (exact up to fp reassociation):
//   z_0 = x@wd.T + bd                               [B,16]
//   m'_t = relu(z_t) * prog_t
//   z_{t+1} = z_t + m'_t @ A + c,   A = wu.T@wd.T (STEP-INVARIANT), c = bu@wd.T
//   R = sum_t m'_t ;  out = x + R@wu.T + 64*bu
// TWO rows per thread; z column-packed as 8x f32x2 (fma.rn.f32x2).
// A rows 0..11 stream from __constant__ (LDC port), rows 12..16 (incl. c)
// + prog from shared (LDS port) — both ports stay under the fma floor.

#define HDIM 128
#define LSTEPS 64

struct Consts {
    float Arow[17][16];        // rows 0..15 = A[j][i]; row 16 = c[i]
    float wd2[128][16];        // wd2[h][i] = wd[i][h]
    float prog[LSTEPS][16];
    float wupc[64][16][2];     // wupc[hp][j] = {wu[2hp][j], wu[2hp+1][j]}
    float bd[16];
    float bu64[128];           // 64*bu[h]
};
__device__ Consts g_c;

__constant__ ulonglong2 cA[17][4];   // copy of Arow (1088 B)

// shared layout (floats): tile 256*33=8448 | persist (Arow..bu64) 5536
#define TILE_FLOATS 8448
#define PERSIST_FLOATS 5536
#define SMEM_FLOATS (TILE_FLOATS + PERSIST_FLOATS)   // 13984
#define SMEM_BYTES (SMEM_FLOATS * 4)                 // 55936

__global__ void setup_kernel(const float* __restrict__ prog,
                             const float* __restrict__ wd,
                             const float* __restrict__ bd,
                             const float* __restrict__ wu,
                             const float* __restrict__ bu) {
    int tid = threadIdx.x;  // 256 threads, 1 block
    {   // A[j][i] = sum_h wu[h][j] * wd[i][h]
        int j = tid >> 4, i = tid & 15;
        float s = 0.f;
        #pragma unroll 8
        for (int h = 0; h < HDIM; ++h) s += wu[h * 16 + j] * wd[i * HDIM + h];
        g_c.Arow[j][i] = s;
    }
    if (tid < 16) {
        int i = tid;
        float s = 0.f;
        #pragma unroll 8
        for (int h = 0; h < HDIM; ++h) s += bu[h] * wd[i * HDIM + h];
        g_c.Arow[16][i] = s;   // c row
        g_c.bd[i] = bd[i];
    }
    for (int idx = tid; idx < LSTEPS * 16; idx += 256)
        g_c.prog[idx >> 4][idx & 15] = prog[idx];
    for (int idx = tid; idx < 128 * 16; idx += 256) {
        int h = idx >> 4, i = idx & 15;
        g_c.wd2[h][i] = wd[i * HDIM + h];
    }
    for (int idx = tid; idx < 64 * 16; idx += 256) {
        int hp = idx >> 4, j = idx & 15;
        g_c.wupc[hp][j][0] = wu[(2 * hp) * 16 + j];
        g_c.wupc[hp][j][1] = wu[(2 * hp + 1) * 16 + j];
    }
    for (int idx = tid; idx < 128; idx += 256) g_c.bu64[idx] = 64.f * bu[idx];
}

// ---- packed f32x2 helpers ----
typedef unsigned long long u64;

__device__ __forceinline__ u64 pk(float x, float y) {
    u64 r; asm("mov.b64 %0, {%1, %2};" : "=l"(r) : "f"(x), "f"(y)); return r;
}
__device__ __forceinline__ void upk(u64 v, float& x, float& y) {
    asm("mov.b64 {%0, %1}, %2;" : "=f"(x), "=f"(y) : "l"(v));
}
__device__ __forceinline__ u64 fma2(u64 a, u64 b, u64 c) {
    u64 d; asm("fma.rn.f32x2 %0, %1, %2, %3;" : "=l"(d) : "l"(a), "l"(b), "l"(c)); return d;
}
__device__ __forceinline__ u64 add2(u64 a, u64 b) {
    u64 d; asm("add.rn.f32x2 %0, %1, %2;" : "=l"(d) : "l"(a), "l"(b)); return d;
}

// phase A: z += x_row @ wd.T for one 256-row group
__device__ __forceinline__ void phaseA(const float* __restrict__ xg,
                                       float* tile, const float* s_wd2,
                                       u64 z2[8], int tid) {
    for (int ch = 0; ch < 4; ++ch) {
        __syncthreads();
        for (int f = tid; f < 8192; f += 256) {
            int r = f >> 5, c = f & 31;
            tile[r * 33 + c] = xg[(long)r * HDIM + ch * 32 + c];
        }
        __syncthreads();
        #pragma unroll
        for (int c = 0; c < 32; ++c) {
            float xv = tile[tid * 33 + c];
            u64 xs = pk(xv, xv);
            const ulonglong2* w = (const ulonglong2*)(s_wd2 + (ch * 32 + c) * 16);
            #pragma unroll
            for (int kk = 0; kk < 4; ++kk) {
                ulonglong2 wv = w[kk];
                z2[2 * kk]     = fma2(xs, wv.x, z2[2 * kk]);
                z2[2 * kk + 1] = fma2(xs, wv.y, z2[2 * kk + 1]);
            }
        }
    }
}

// phase C: out_row = x_row + R @ wu.T + 64*bu for one 256-row group
__device__ __forceinline__ void phaseC(const float* __restrict__ xg,
                                       float* __restrict__ og,
                                       float* tile, const float* s_wupc,
                                       const float* s_bu,
                                       const u64 Racc2[8], int tid) {
    u64 Rs[16];
    #pragma unroll
    for (int k = 0; k < 8; ++k) {
        float r0, r1;
        upk(Racc2[k], r0, r1);
        Rs[2 * k]     = pk(r0, r0);
        Rs[2 * k + 1] = pk(r1, r1);
    }
    for (int ch = 0; ch < 4; ++ch) {
        __syncthreads();
        #pragma unroll
        for (int hp = 0; hp < 16; ++hp) {
            int h2 = ch * 16 + hp;
            u64 acc = *(const u64*)(s_bu + h2 * 2);
            const ulonglong2* urow = (const ulonglong2*)(s_wupc + h2 * 32);
            #pragma unroll
            for (int jj = 0; jj < 8; ++jj) {
                ulonglong2 u = urow[jj];
                acc = fma2(Rs[2 * jj],     u.x, acc);
                acc = fma2(Rs[2 * jj + 1], u.y, acc);
            }
            float y0, y1;
            upk(acc, y0, y1);
            tile[tid * 33 + 2 * hp]     = y0;
            tile[tid * 33 + 2 * hp + 1] = y1;
        }
        __syncthreads();
        for (int f = tid; f < 8192; f += 256) {
            int r = f >> 5, c = f & 31;
            long g = (long)r * HDIM + ch * 32 + c;
            og[g] = xg[g] + tile[r * 33 + c];
        }
    }
}

__global__ __launch_bounds__(256, 2)
void proc_kernel(const float* __restrict__ x, float* __restrict__ out) {
    extern __shared__ float sm[];
    float* tile   = sm;                     // 8448
    float* s_A    = sm + TILE_FLOATS;       // 272 (rows 12..16 used)
    float* s_wd2  = s_A + 272;              // 2048
    float* s_prog = s_wd2 + 2048;           // 1024
    float* s_wupc = s_prog + 1024;          // 2048
    float* s_bd   = s_wupc + 2048;          // 16
    float* s_bu   = s_bd + 16;              // 128

    int tid = threadIdx.x;

    // copy persistent consts (Arow..bu64 contiguous in Consts)
    {
        const float4* src = (const float4*)&g_c.Arow[0][0];
        float4* dst = (float4*)s_A;
        for (int i = tid; i < PERSIST_FLOATS / 4; i += 256) dst[i] = src[i];
    }
    __syncthreads();

    long row0 = (long)blockIdx.x * 512;     // 512 rows/block (2 per thread)
    const float* xa = x + row0 * HDIM;
    const float* xb = xa + 256L * HDIM;
    float* oa = out + row0 * HDIM;
    float* ob = oa + 256L * HDIM;

    u64 za[8], zb[8];
    #pragma unroll
    for (int k = 0; k < 8; ++k) {
        u64 b = *(const u64*)(s_bd + 2 * k);
        za[k] = b; zb[k] = b;
    }

    // ---- phase A for both row groups ----
    phaseA(xa, tile, s_wd2, za, tid);
    phaseA(xb, tile, s_wd2, zb, tid);
    __syncthreads();

    // ---- phase B: 64 steps; A operands split LDC (rows 0..11) / LDS ----
    u64 Ra[8], Rb[8];
    #pragma unroll
    for (int k = 0; k < 8; ++k) { Ra[k] = 0ull; Rb[k] = 0ull; }
    const u64 one2 = pk(1.f, 1.f);

    #pragma unroll 1
    for (int t = 0; t < LSTEPS; ++t) {
        // prog for this step (4x LDS.128)
        const float4* prq = (const float4*)(s_prog + t * 16);
        float4 p0 = prq[0], p1 = prq[1], p2 = prq[2], p3 = prq[3];
        float pr[16] = {p0.x, p0.y, p0.z, p0.w, p1.x, p1.y, p1.z, p1.w,
                        p2.x, p2.y, p2.z, p2.w, p3.x, p3.y, p3.z, p3.w};

        // m' = relu(z) * prog
        float ma[16], mb[16];
        #pragma unroll
        for (int k = 0; k < 8; ++k) {
            float u, v;
            upk(za[k], u, v);
            ma[2 * k]     = fmaxf(u, 0.f) * pr[2 * k];
            ma[2 * k + 1] = fmaxf(v, 0.f) * pr[2 * k + 1];
            upk(zb[k], u, v);
            mb[2 * k]     = fmaxf(u, 0.f) * pr[2 * k];
            mb[2 * k + 1] = fmaxf(v, 0.f) * pr[2 * k + 1];
        }
        // R += m'
        #pragma unroll
        for (int k = 0; k < 8; ++k) {
            Ra[k] = add2(Ra[k], pk(ma[2 * k], ma[2 * k + 1]));
            Rb[k] = add2(Rb[k], pk(mb[2 * k], mb[2 * k + 1]));
        }
        // z += m' @ A + c  (row 16 of A is c, multiplier 1.0)
        #pragma unroll
        for (int j = 0; j < 17; ++j) {
            u64 mja = (j < 16) ? pk(ma[j], ma[j]) : one2;
            u64 mjb = (j < 16) ? pk(mb[j], mb[j]) : one2;
            ulonglong2 r0, r1;
            if (j < 12) {            // constant port (t-invariant, hoistable)
                r0 = cA[j][0]; r1 = cA[j][1];
            } else {                  // shared port
                const ulonglong2* arow = (const ulonglong2*)(s_A + j * 16);
                r0 = arow[0]; r1 = arow[1];
            }
            za[0] = fma2(mja, r0.x, za[0]);  za[1] = fma2(mja, r0.y, za[1]);
            zb[0] = fma2(mjb, r0.x, zb[0]);  zb[1] = fma2(mjb, r0.y, zb[1]);
            za[2] = fma2(mja, r1.x, za[2]);  za[3] = fma2(mja, r1.y, za[3]);
            zb[2] = fma2(mjb, r1.x, zb[2]);  zb[3] = fma2(mjb, r1.y, zb[3]);
            ulonglong2 r2, r3;
            if (j < 12) {
                r2 = cA[j][2]; r3 = cA[j][3];
            } else {
                const ulonglong2* arow = (const ulonglong2*)(s_A + j * 16);
                r2 = arow[2]; r3 = arow[3];
            }
            za[4] = fma2(mja, r2.x, za[4]);  za[5] = fma2(mja, r2.y, za[5]);
            zb[4] = fma2(mjb, r2.x, zb[4]);  zb[5] = fma2(mjb, r2.y, zb[5]);
            za[6] = fma2(mja, r3.x, za[6]);  za[7] = fma2(mja, r3.y, za[7]);
            zb[6] = fma2(mjb, r3.x, zb[6]);  zb[7] = fma2(mjb, r3.y, zb[7]);
        }
    }

    // ---- phase C for both row groups ----
    phaseC(xa, oa, tile, s_wupc, s_bu, Ra, tid);
    phaseC(xb, ob, tile, s_wupc, s_bu, Rb, tid);
}

extern "C" void kernel_launch(void* const* d_in, const int* in_sizes, int n_in,
                              void* d_out, int out_size) {
    const float* x    = (const float*)d_in[0];
    const float* prog = (const float*)d_in[1];
    const float* wd   = (const float*)d_in[2];
    const float* bd   = (const float*)d_in[3];
    const float* wu   = (const float*)d_in[4];
    const float* bu   = (const float*)d_in[5];
    float* out = (float*)d_out;

    cudaFuncSetAttribute(proc_kernel,
                         cudaFuncAttributeMaxDynamicSharedMemorySize, SMEM_BYTES);

    setup_kernel<<<1, 256>>>(prog, wd, bd, wu, bu);

    // copy A (17x16 floats, Arow is at offset 0 of g_c) into constant memory
    void* gc_ptr = nullptr;
    cudaGetSymbolAddress(&gc_ptr, g_c);
    cudaMemcpyToSymbolAsync(cA, gc_ptr, 17 * 16 * sizeof(float), 0,
                            cudaMemcpyDeviceToDevice);

    int rows = in_sizes[0] / HDIM;          // 262144
    int blocks = rows / 512;                // 512
    proc_kernel<<<blocks, 256, SMEM_BYTES>>>(x, out);
}

// round 10
// speedup vs baseline: 1.5180x; 1.5113x over previous
#include <cuda_runtime.h>
#include <cuda_bf16.h>
#include <cstdint>

// ProcessorNet reduction (exact up to fp reassociation):
//   z_0 = x@wd.T + bd                               [B,16]
//   m_t = relu(z_t + t*c_reconstructed) * prog_t ; R += m_t
//   z   += m_t @ A       (A = wu.T@wd.T, c = bu@wd.T kept OUT of the MMA)
//   out = x + R@wu.T + 64*bu
// Phase B on tensor cores: mma.sync.m16n8k16 bf16, A-matrix resident in
// registers as B-fragments, z resident as D-fragments (D layout == A layout).
// bf16 hi/lo split: mh@Ah + mh@Al + ml@Ah  (error ~2^-18 per step).

#define HDIM 128
#define LSTEPS 64

struct Consts {
    float A[16][16];           // A[j][i]
    float wd2[128][16];        // wd2[h][i] = wd[i][h]
    float prog[LSTEPS][16];
    float wupc[64][16][2];     // {wu[2hp][j], wu[2hp+1][j]}
    float bd[16];
    float c[16];               // bu @ wd.T
    float bu64[128];           // 64*bu
};
__device__ Consts g_c;

#define REGION0_FLOATS 8448    // tile 256*33 | z_s/R_s 256*18
#define PERSIST_FLOATS 5536    // A..bu64 contiguous
#define SMEM_FLOATS (REGION0_FLOATS + PERSIST_FLOATS)
#define SMEM_BYTES (SMEM_FLOATS * 4)   // 55936

__global__ void setup_kernel(const float* __restrict__ prog,
                             const float* __restrict__ wd,
                             const float* __restrict__ bd,
                             const float* __restrict__ wu,
                             const float* __restrict__ bu) {
    int tid = threadIdx.x;  // 256
    {   // A[j][i] = sum_h wu[h][j] * wd[i][h]
        int j = tid >> 4, i = tid & 15;
        float s = 0.f;
        #pragma unroll 8
        for (int h = 0; h < HDIM; ++h) s += wu[h * 16 + j] * wd[i * HDIM + h];
        g_c.A[j][i] = s;
    }
    if (tid < 16) {
        int i = tid;
        float s = 0.f;
        #pragma unroll 8
        for (int h = 0; h < HDIM; ++h) s += bu[h] * wd[i * HDIM + h];
        g_c.c[i] = s;
        g_c.bd[i] = bd[i];
    }
    for (int idx = tid; idx < LSTEPS * 16; idx += 256)
        g_c.prog[idx >> 4][idx & 15] = prog[idx];
    for (int idx = tid; idx < 128 * 16; idx += 256) {
        int h = idx >> 4, i = idx & 15;
        g_c.wd2[h][i] = wd[i * HDIM + h];
    }
    for (int idx = tid; idx < 64 * 16; idx += 256) {
        int hp = idx >> 4, j = idx & 15;
        g_c.wupc[hp][j][0] = wu[(2 * hp) * 16 + j];
        g_c.wupc[hp][j][1] = wu[(2 * hp + 1) * 16 + j];
    }
    for (int idx = tid; idx < 128; idx += 256) g_c.bu64[idx] = 64.f * bu[idx];
}

// ---- helpers ----
typedef unsigned long long u64;
__device__ __forceinline__ u64 pk(float x, float y) {
    u64 r; asm("mov.b64 %0, {%1, %2};" : "=l"(r) : "f"(x), "f"(y)); return r;
}
__device__ __forceinline__ void upk(u64 v, float& x, float& y) {
    asm("mov.b64 {%0, %1}, %2;" : "=f"(x), "=f"(y) : "l"(v));
}
__device__ __forceinline__ u64 fma2(u64 a, u64 b, u64 c) {
    u64 d; asm("fma.rn.f32x2 %0, %1, %2, %3;" : "=l"(d) : "l"(a), "l"(b), "l"(c)); return d;
}
__device__ __forceinline__ uint32_t pkbf(float a, float b) {   // low=a, high=b
    __nv_bfloat162 h = __floats2bfloat162_rn(a, b);
    return *reinterpret_cast<uint32_t*>(&h);
}
__device__ __forceinline__ void mma_bf16(float* d, const uint32_t* a,
                                         const uint32_t* b) {
    asm volatile(
        "mma.sync.aligned.m16n8k16.row.col.f32.bf16.bf16.f32 "
        "{%0,%1,%2,%3}, {%4,%5,%6,%7}, {%8,%9}, {%0,%1,%2,%3};\n"
        : "+f"(d[0]), "+f"(d[1]), "+f"(d[2]), "+f"(d[3])
        : "r"(a[0]), "r"(a[1]), "r"(a[2]), "r"(a[3]), "r"(b[0]), "r"(b[1]));
}

__global__ __launch_bounds__(256, 2)
void proc_kernel(const float* __restrict__ x, float* __restrict__ out) {
    extern __shared__ float sm[];
    float* region0 = sm;                 // tile (A/C) | z_s/R_s (stride 18)
    float* s_A    = sm + REGION0_FLOATS; // 256
    float* s_wd2  = s_A + 256;           // 2048
    float* s_prog = s_wd2 + 2048;        // 1024
    float* s_wupc = s_prog + 1024;       // 2048
    float* s_bd   = s_wupc + 2048;       // 16
    float* s_c    = s_bd + 16;           // 16
    float* s_bu   = s_c + 16;            // 128

    int tid = threadIdx.x;
    {
        const float4* src = (const float4*)&g_c.A[0][0];
        float4* dst = (float4*)s_A;
        for (int i = tid; i < PERSIST_FLOATS / 4; i += 256) dst[i] = src[i];
    }
    __syncthreads();

    long row0 = (long)blockIdx.x * 256;
    const float* xr = x + row0 * HDIM;
    float* outr = out + row0 * HDIM;

    // ---- phase A: z = x@wd.T + bd (1 row/thread, f32x2) ----
    u64 z2[8];
    #pragma unroll
    for (int k = 0; k < 8; ++k) z2[k] = *(const u64*)(s_bd + 2 * k);
    for (int ch = 0; ch < 4; ++ch) {
        __syncthreads();
        for (int f = tid; f < 8192; f += 256) {
            int r = f >> 5, c = f & 31;
            region0[r * 33 + c] = xr[(long)r * HDIM + ch * 32 + c];
        }
        __syncthreads();
        #pragma unroll
        for (int c = 0; c < 32; ++c) {
            float xv = region0[tid * 33 + c];
            u64 xs = pk(xv, xv);
            const ulonglong2* w = (const ulonglong2*)(s_wd2 + (ch * 32 + c) * 16);
            #pragma unroll
            for (int kk = 0; kk < 4; ++kk) {
                ulonglong2 wv = w[kk];
                z2[2 * kk]     = fma2(xs, wv.x, z2[2 * kk]);
                z2[2 * kk + 1] = fma2(xs, wv.y, z2[2 * kk + 1]);
            }
        }
    }

    // ---- stage z into z_s[row][col], stride 18 ----
    __syncthreads();   // everyone done reading tile
    #pragma unroll
    for (int k = 0; k < 8; ++k) {
        float a, b; upk(z2[k], a, b);
        *(float2*)&region0[tid * 18 + 2 * k] = make_float2(a, b);
    }
    __syncwarp();      // rows of a warp are staged by that same warp

    // ---- fragment setup ----
    int lane = tid & 31, wrp = tid >> 5;
    int g = lane >> 2, tg = lane & 3;
    int rb = wrp * 32;         // this warp's 32 rows (2 tiles of 16)
    int cbl = 2 * tg;          // low col within an 8-col fragment half

    // z/R fragments: [tile][colhalf][d0..d3]
    // d0: (row g, col cbl) d1: (g, cbl+1) d2: (g+8, cbl) d3: (g+8, cbl+1)
    float zf[2][2][4], Rf[2][2][4];
    #pragma unroll
    for (int tl = 0; tl < 2; ++tl) {
        int r0 = rb + tl * 16 + g, r1 = r0 + 8;
        #pragma unroll
        for (int cf = 0; cf < 2; ++cf) {
            int cb = cf * 8 + cbl;
            float2 lo = *(const float2*)&region0[r0 * 18 + cb];
            float2 hi = *(const float2*)&region0[r1 * 18 + cb];
            zf[tl][cf][0] = lo.x; zf[tl][cf][1] = lo.y;
            zf[tl][cf][2] = hi.x; zf[tl][cf][3] = hi.y;
            Rf[tl][cf][0] = Rf[tl][cf][1] = Rf[tl][cf][2] = Rf[tl][cf][3] = 0.f;
        }
    }

    // B fragments of A (col-major B): b0={B[k0][n],B[k0+1][n]}, b1={B[k0+8][n],B[k0+9][n]}
    // n-chunk nc: n = g + nc*8 ; B[k][n] = A[k][n]
    uint32_t bh[2][2], bl[2][2];
    {
        int k0 = cbl;
        #pragma unroll
        for (int nc = 0; nc < 2; ++nc) {
            int n = g + nc * 8;
            float a0 = s_A[k0 * 16 + n],       a1 = s_A[(k0 + 1) * 16 + n];
            float a8 = s_A[(k0 + 8) * 16 + n], a9 = s_A[(k0 + 9) * 16 + n];
            uint32_t h0 = pkbf(a0, a1), h1 = pkbf(a8, a9);
            bh[nc][0] = h0; bh[nc][1] = h1;
            __nv_bfloat162 hb0 = *reinterpret_cast<__nv_bfloat162*>(&h0);
            __nv_bfloat162 hb1 = *reinterpret_cast<__nv_bfloat162*>(&h1);
            bl[nc][0] = pkbf(a0 - __low2float(hb0), a1 - __high2float(hb0));
            bl[nc][1] = pkbf(a8 - __low2float(hb1), a9 - __high2float(hb1));
        }
    }

    // c columns for this lane (same for both tiles, rows share cols)
    float cc[2][2] = {{s_c[cbl], s_c[cbl + 1]}, {s_c[8 + cbl], s_c[8 + cbl + 1]}};
    float zc[2][2] = {{0.f, 0.f}, {0.f, 0.f}};

    // ---- phase B: 64 steps on tensor cores ----
    #pragma unroll 1
    for (int t = 0; t < LSTEPS; ++t) {
        float2 pa = *(const float2*)&s_prog[t * 16 + cbl];
        float2 pb = *(const float2*)&s_prog[t * 16 + 8 + cbl];
        float pr[2][2] = {{pa.x, pa.y}, {pb.x, pb.y}};

        #pragma unroll
        for (int tl = 0; tl < 2; ++tl) {
            float mv[2][4];
            #pragma unroll
            for (int cf = 0; cf < 2; ++cf)
                #pragma unroll
                for (int d = 0; d < 4; ++d) {
                    float zt = zf[tl][cf][d] + zc[cf][d & 1];
                    float m = fmaxf(zt, 0.f) * pr[cf][d & 1];
                    Rf[tl][cf][d] += m;
                    mv[cf][d] = m;
                }
            // pack A-operand: a0=(g,k cbl..+1) a1=(g+8,same) a2=(g,k+8..) a3=(g+8,..)
            uint32_t ah[4], al[4];
            ah[0] = pkbf(mv[0][0], mv[0][1]);
            ah[1] = pkbf(mv[0][2], mv[0][3]);
            ah[2] = pkbf(mv[1][0], mv[1][1]);
            ah[3] = pkbf(mv[1][2], mv[1][3]);
            #pragma unroll
            for (int q = 0; q < 4; ++q) {
                __nv_bfloat162 hb = *reinterpret_cast<__nv_bfloat162*>(&ah[q]);
                int cf = q >> 1, dd = (q & 1) * 2;
                al[q] = pkbf(mv[cf][dd] - __low2float(hb),
                             mv[cf][dd + 1] - __high2float(hb));
            }
            // z += mh@Ah + mh@Al + ml@Ah   (per 8-col half)
            mma_bf16(zf[tl][0], ah, bh[0]);
            mma_bf16(zf[tl][0], ah, bl[0]);
            mma_bf16(zf[tl][0], al, bh[0]);
            mma_bf16(zf[tl][1], ah, bh[1]);
            mma_bf16(zf[tl][1], ah, bl[1]);
            mma_bf16(zf[tl][1], al, bh[1]);
        }
        #pragma unroll
        for (int cf = 0; cf < 2; ++cf) {
            zc[cf][0] += cc[cf][0];
            zc[cf][1] += cc[cf][1];
        }
    }

    // ---- stage R back to R_s (same warp-local mapping) ----
    #pragma unroll
    for (int tl = 0; tl < 2; ++tl) {
        int r0 = rb + tl * 16 + g, r1 = r0 + 8;
        #pragma unroll
        for (int cf = 0; cf < 2; ++cf) {
            int cb = cf * 8 + cbl;
            *(float2*)&region0[r0 * 18 + cb] = make_float2(Rf[tl][cf][0], Rf[tl][cf][1]);
            *(float2*)&region0[r1 * 18 + cb] = make_float2(Rf[tl][cf][2], Rf[tl][cf][3]);
        }
    }
    __syncwarp();

    // each thread picks up its row's R (warp-local) and splats
    u64 Rs[16];
    #pragma unroll
    for (int k = 0; k < 8; ++k) {
        float2 v = *(const float2*)&region0[tid * 18 + 2 * k];
        Rs[2 * k]     = pk(v.x, v.x);
        Rs[2 * k + 1] = pk(v.y, v.y);
    }

    // ---- phase C: out = x + R@wu.T + 64*bu ----
    for (int ch = 0; ch < 4; ++ch) {
        __syncthreads();
        #pragma unroll
        for (int hp = 0; hp < 16; ++hp) {
            int h2 = ch * 16 + hp;
            u64 acc = *(const u64*)(s_bu + h2 * 2);
            const ulonglong2* urow = (const ulonglong2*)(s_wupc + h2 * 32);
            #pragma unroll
            for (int jj = 0; jj < 8; ++jj) {
                ulonglong2 u = urow[jj];
                acc = fma2(Rs[2 * jj],     u.x, acc);
                acc = fma2(Rs[2 * jj + 1], u.y, acc);
            }
            float y0, y1;
            upk(acc, y0, y1);
            region0[tid * 33 + 2 * hp]     = y0;
            region0[tid * 33 + 2 * hp + 1] = y1;
        }
        __syncthreads();
        for (int f = tid; f < 8192; f += 256) {
            int r = f >> 5, c = f & 31;
            long gg = (long)r * HDIM + ch * 32 + c;
            outr[gg] = xr[gg] + region0[r * 33 + c];
        }
    }
}

extern "C" void kernel_launch(void* const* d_in, const int* in_sizes, int n_in,
                              void* d_out, int out_size) {
    const float* x    = (const float*)d_in[0];
    const float* prog = (const float*)d_in[1];
    const float* wd   = (const float*)d_in[2];
    const float* bd   = (const float*)d_in[3];
    const float* wu   = (const float*)d_in[4];
    const float* bu   = (const float*)d_in[5];
    float* out = (float*)d_out;

    cudaFuncSetAttribute(proc_kernel,
                         cudaFuncAttributeMaxDynamicSharedMemorySize, SMEM_BYTES);

    setup_kernel<<<1, 256>>>(prog, wd, bd, wu, bu);

    int rows = in_sizes[0] / HDIM;          // 262144
    int blocks = rows / 256;                // 1024
    proc_kernel<<<blocks, 256, SMEM_BYTES>>>(x, out);
}

// round 11
// speedup vs baseline: 1.7405x; 1.1466x over previous
#include <cuda_runtime.h>
#include <cuda_bf16.h>
#include <cstdint>

// ProcessorNet reduction (exact up to fp reassociation):
//   z_0 = x@wd.T + bd ; m_t = relu(z_t + t*c)*prog_t ; R += m_t ; z += m_t@A
//   out = x + R@wu.T + 64*bu     (A = wu.T@wd.T, c = bu@wd.T)
// Phase B on tensor cores (mma.sync.m16n8k16 bf16):
//   z, R resident as D-fragments; A resident as B-fragments (hi+lo split);
//   R accumulated via identity-B MMAs; "+c" reconstructed exactly in regs.
//   z += mh@Ah + mh@Al ; R += mh@I   (mh = bf16(m), err ~1e-5 overall)

#define HDIM 128
#define LSTEPS 64

struct Consts {
    float A[16][16];           // A[j][i]
    float wd2[128][16];        // wd2[h][i] = wd[i][h]
    float prog[LSTEPS][16];
    float wupc[64][16][2];     // {wu[2hp][j], wu[2hp+1][j]}
    float bd[16];
    float c[16];               // bu @ wd.T
    float bu64[128];           // 64*bu
};
__device__ Consts g_c;

#define REGION0_FLOATS 8448    // tile 256*33 | z_s/R_s 256*18
#define PERSIST_FLOATS 5536
#define SMEM_FLOATS (REGION0_FLOATS + PERSIST_FLOATS)
#define SMEM_BYTES (SMEM_FLOATS * 4)   // 55936

__global__ void setup_kernel(const float* __restrict__ prog,
                             const float* __restrict__ wd,
                             const float* __restrict__ bd,
                             const float* __restrict__ wu,
                             const float* __restrict__ bu) {
    int tid = threadIdx.x;  // 256
    {   // A[j][i] = sum_h wu[h][j] * wd[i][h]
        int j = tid >> 4, i = tid & 15;
        float s = 0.f;
        #pragma unroll 8
        for (int h = 0; h < HDIM; ++h) s += wu[h * 16 + j] * wd[i * HDIM + h];
        g_c.A[j][i] = s;
    }
    if (tid < 16) {
        int i = tid;
        float s = 0.f;
        #pragma unroll 8
        for (int h = 0; h < HDIM; ++h) s += bu[h] * wd[i * HDIM + h];
        g_c.c[i] = s;
        g_c.bd[i] = bd[i];
    }
    for (int idx = tid; idx < LSTEPS * 16; idx += 256)
        g_c.prog[idx >> 4][idx & 15] = prog[idx];
    for (int idx = tid; idx < 128 * 16; idx += 256) {
        int h = idx >> 4, i = idx & 15;
        g_c.wd2[h][i] = wd[i * HDIM + h];
    }
    for (int idx = tid; idx < 64 * 16; idx += 256) {
        int hp = idx >> 4, j = idx & 15;
        g_c.wupc[hp][j][0] = wu[(2 * hp) * 16 + j];
        g_c.wupc[hp][j][1] = wu[(2 * hp + 1) * 16 + j];
    }
    for (int idx = tid; idx < 128; idx += 256) g_c.bu64[idx] = 64.f * bu[idx];
}

// ---- helpers ----
typedef unsigned long long u64;
__device__ __forceinline__ u64 pk(float x, float y) {
    u64 r; asm("mov.b64 %0, {%1, %2};" : "=l"(r) : "f"(x), "f"(y)); return r;
}
__device__ __forceinline__ void upk(u64 v, float& x, float& y) {
    asm("mov.b64 {%0, %1}, %2;" : "=f"(x), "=f"(y) : "l"(v));
}
__device__ __forceinline__ u64 fma2(u64 a, u64 b, u64 c) {
    u64 d; asm("fma.rn.f32x2 %0, %1, %2, %3;" : "=l"(d) : "l"(a), "l"(b), "l"(c)); return d;
}
__device__ __forceinline__ uint32_t pkbf(float a, float b) {   // low=a, high=b
    __nv_bfloat162 h = __floats2bfloat162_rn(a, b);
    return *reinterpret_cast<uint32_t*>(&h);
}
__device__ __forceinline__ void mma_bf16(float* d, const uint32_t* a,
                                         const uint32_t* b) {
    asm volatile(
        "mma.sync.aligned.m16n8k16.row.col.f32.bf16.bf16.f32 "
        "{%0,%1,%2,%3}, {%4,%5,%6,%7}, {%8,%9}, {%0,%1,%2,%3};\n"
        : "+f"(d[0]), "+f"(d[1]), "+f"(d[2]), "+f"(d[3])
        : "r"(a[0]), "r"(a[1]), "r"(a[2]), "r"(a[3]), "r"(b[0]), "r"(b[1]));
}

__global__ __launch_bounds__(256, 2)
void proc_kernel(const float* __restrict__ x, float* __restrict__ out) {
    extern __shared__ float sm[];
    float* region0 = sm;                 // tile (A/C) | z_s/R_s (stride 18)
    float* s_A    = sm + REGION0_FLOATS; // 256
    float* s_wd2  = s_A + 256;           // 2048
    float* s_prog = s_wd2 + 2048;        // 1024
    float* s_wupc = s_prog + 1024;       // 2048
    float* s_bd   = s_wupc + 2048;       // 16
    float* s_c    = s_bd + 16;           // 16
    float* s_bu   = s_c + 16;            // 128

    int tid = threadIdx.x;
    {
        const float4* src = (const float4*)&g_c.A[0][0];
        float4* dst = (float4*)s_A;
        for (int i = tid; i < PERSIST_FLOATS / 4; i += 256) dst[i] = src[i];
    }
    __syncthreads();

    long row0 = (long)blockIdx.x * 256;
    const float* xr = x + row0 * HDIM;
    float* outr = out + row0 * HDIM;

    // ---- phase A: z = x@wd.T + bd (1 row/thread, f32x2) ----
    u64 z2[8];
    #pragma unroll
    for (int k = 0; k < 8; ++k) z2[k] = *(const u64*)(s_bd + 2 * k);
    for (int ch = 0; ch < 4; ++ch) {
        __syncthreads();
        for (int f = tid; f < 8192; f += 256) {
            int r = f >> 5, c = f & 31;
            region0[r * 33 + c] = xr[(long)r * HDIM + ch * 32 + c];
        }
        __syncthreads();
        #pragma unroll
        for (int c = 0; c < 32; ++c) {
            float xv = region0[tid * 33 + c];
            u64 xs = pk(xv, xv);
            const ulonglong2* w = (const ulonglong2*)(s_wd2 + (ch * 32 + c) * 16);
            #pragma unroll
            for (int kk = 0; kk < 4; ++kk) {
                ulonglong2 wv = w[kk];
                z2[2 * kk]     = fma2(xs, wv.x, z2[2 * kk]);
                z2[2 * kk + 1] = fma2(xs, wv.y, z2[2 * kk + 1]);
            }
        }
    }

    // ---- stage z into z_s[row][col], stride 18 ----
    __syncthreads();
    #pragma unroll
    for (int k = 0; k < 8; ++k) {
        float a, b; upk(z2[k], a, b);
        *(float2*)&region0[tid * 18 + 2 * k] = make_float2(a, b);
    }
    __syncwarp();

    // ---- fragment setup ----
    int lane = tid & 31, wrp = tid >> 5;
    int g = lane >> 2, tg = lane & 3;
    int rb = wrp * 32;
    int cbl = 2 * tg;

    // z/R fragments: d0:(g,cbl) d1:(g,cbl+1) d2:(g+8,cbl) d3:(g+8,cbl+1)
    float zf[2][2][4], Rf[2][2][4];
    #pragma unroll
    for (int tl = 0; tl < 2; ++tl) {
        int r0 = rb + tl * 16 + g, r1 = r0 + 8;
        #pragma unroll
        for (int cf = 0; cf < 2; ++cf) {
            int cb = cf * 8 + cbl;
            float2 lo = *(const float2*)&region0[r0 * 18 + cb];
            float2 hi = *(const float2*)&region0[r1 * 18 + cb];
            zf[tl][cf][0] = lo.x; zf[tl][cf][1] = lo.y;
            zf[tl][cf][2] = hi.x; zf[tl][cf][3] = hi.y;
            Rf[tl][cf][0] = Rf[tl][cf][1] = Rf[tl][cf][2] = Rf[tl][cf][3] = 0.f;
        }
    }

    // B fragments of A (col-major): b0={B[k0][n],B[k0+1][n]}, b1={B[k0+8][n],...}
    uint32_t bh[2][2], bl[2][2], bI[2][2];
    {
        int k0 = cbl;
        #pragma unroll
        for (int nc = 0; nc < 2; ++nc) {
            int n = g + nc * 8;
            float a0 = s_A[k0 * 16 + n],       a1 = s_A[(k0 + 1) * 16 + n];
            float a8 = s_A[(k0 + 8) * 16 + n], a9 = s_A[(k0 + 9) * 16 + n];
            uint32_t h0 = pkbf(a0, a1), h1 = pkbf(a8, a9);
            bh[nc][0] = h0; bh[nc][1] = h1;
            __nv_bfloat162 hb0 = *reinterpret_cast<__nv_bfloat162*>(&h0);
            __nv_bfloat162 hb1 = *reinterpret_cast<__nv_bfloat162*>(&h1);
            bl[nc][0] = pkbf(a0 - __low2float(hb0), a1 - __high2float(hb0));
            bl[nc][1] = pkbf(a8 - __low2float(hb1), a9 - __high2float(hb1));
            // identity block for R: B[k][n'] = (k == nc*8 + n') ; n' = g
            int j = nc * 8 + g;
            bI[nc][0] = pkbf((k0 == j) ? 1.f : 0.f, (k0 + 1 == j) ? 1.f : 0.f);
            bI[nc][1] = pkbf((k0 + 8 == j) ? 1.f : 0.f, (k0 + 9 == j) ? 1.f : 0.f);
        }
    }

    float cc[2][2] = {{s_c[cbl], s_c[cbl + 1]}, {s_c[8 + cbl], s_c[8 + cbl + 1]}};
    float zc[2][2] = {{0.f, 0.f}, {0.f, 0.f}};

    // ---- phase B: 64 steps; z += mh@Ah + mh@Al ; R += mh@I ----
    #pragma unroll 1
    for (int t = 0; t < LSTEPS; ++t) {
        float2 pa = *(const float2*)&s_prog[t * 16 + cbl];
        float2 pb = *(const float2*)&s_prog[t * 16 + 8 + cbl];
        float pr[2][2] = {{pa.x, pa.y}, {pb.x, pb.y}};

        uint32_t ah[2][4];
        #pragma unroll
        for (int tl = 0; tl < 2; ++tl) {
            float mv[2][4];
            #pragma unroll
            for (int cf = 0; cf < 2; ++cf)
                #pragma unroll
                for (int d = 0; d < 4; ++d) {
                    float zt = zf[tl][cf][d] + zc[cf][d & 1];
                    mv[cf][d] = fmaxf(zt, 0.f) * pr[cf][d & 1];
                }
            ah[tl][0] = pkbf(mv[0][0], mv[0][1]);
            ah[tl][1] = pkbf(mv[0][2], mv[0][3]);
            ah[tl][2] = pkbf(mv[1][0], mv[1][1]);
            ah[tl][3] = pkbf(mv[1][2], mv[1][3]);
        }
        // 12 MMAs over 8 independent accumulators
        mma_bf16(zf[0][0], ah[0], bh[0]);
        mma_bf16(zf[0][1], ah[0], bh[1]);
        mma_bf16(zf[1][0], ah[1], bh[0]);
        mma_bf16(zf[1][1], ah[1], bh[1]);
        mma_bf16(Rf[0][0], ah[0], bI[0]);
        mma_bf16(Rf[0][1], ah[0], bI[1]);
        mma_bf16(Rf[1][0], ah[1], bI[0]);
        mma_bf16(Rf[1][1], ah[1], bI[1]);
        mma_bf16(zf[0][0], ah[0], bl[0]);
        mma_bf16(zf[0][1], ah[0], bl[1]);
        mma_bf16(zf[1][0], ah[1], bl[0]);
        mma_bf16(zf[1][1], ah[1], bl[1]);

        #pragma unroll
        for (int cf = 0; cf < 2; ++cf) {
            zc[cf][0] += cc[cf][0];
            zc[cf][1] += cc[cf][1];
        }
    }

    // ---- stage R back to R_s (warp-local mapping) ----
    #pragma unroll
    for (int tl = 0; tl < 2; ++tl) {
        int r0 = rb + tl * 16 + g, r1 = r0 + 8;
        #pragma unroll
        for (int cf = 0; cf < 2; ++cf) {
            int cb = cf * 8 + cbl;
            *(float2*)&region0[r0 * 18 + cb] = make_float2(Rf[tl][cf][0], Rf[tl][cf][1]);
            *(float2*)&region0[r1 * 18 + cb] = make_float2(Rf[tl][cf][2], Rf[tl][cf][3]);
        }
    }
    __syncwarp();

    u64 Rs[16];
    #pragma unroll
    for (int k = 0; k < 8; ++k) {
        float2 v = *(const float2*)&region0[tid * 18 + 2 * k];
        Rs[2 * k]     = pk(v.x, v.x);
        Rs[2 * k + 1] = pk(v.y, v.y);
    }

    // ---- phase C: out = x + R@wu.T + 64*bu ----
    for (int ch = 0; ch < 4; ++ch) {
        __syncthreads();
        #pragma unroll
        for (int hp = 0; hp < 16; ++hp) {
            int h2 = ch * 16 + hp;
            u64 acc = *(const u64*)(s_bu + h2 * 2);
            const ulonglong2* urow = (const ulonglong2*)(s_wupc + h2 * 32);
            #pragma unroll
            for (int jj = 0; jj < 8; ++jj) {
                ulonglong2 u = urow[jj];
                acc = fma2(Rs[2 * jj],     u.x, acc);
                acc = fma2(Rs[2 * jj + 1], u.y, acc);
            }
            float y0, y1;
            upk(acc, y0, y1);
            region0[tid * 33 + 2 * hp]     = y0;
            region0[tid * 33 + 2 * hp + 1] = y1;
        }
        __syncthreads();
        for (int f = tid; f < 8192; f += 256) {
            int r = f >> 5, c = f & 31;
            long gg = (long)r * HDIM + ch * 32 + c;
            outr[gg] = xr[gg] + region0[r * 33 + c];
        }
    }
}

extern "C" void kernel_launch(void* const* d_in, const int* in_sizes, int n_in,
                              void* d_out, int out_size) {
    const float* x    = (const float*)d_in[0];
    const float* prog = (const float*)d_in[1];
    const float* wd   = (const float*)d_in[2];
    const float* bd   = (const float*)d_in[3];
    const float* wu   = (const float*)d_in[4];
    const float* bu   = (const float*)d_in[5];
    float* out = (float*)d_out;

    cudaFuncSetAttribute(proc_kernel,
                         cudaFuncAttributeMaxDynamicSharedMemorySize, SMEM_BYTES);

    setup_kernel<<<1, 256>>>(prog, wd, bd, wu, bu);

    int rows = in_sizes[0] / HDIM;          // 262144
    int blocks = rows / 256;                // 1024
    proc_kernel<<<blocks, 256, SMEM_BYTES>>>(x, out);
}

// round 12
// speedup vs baseline: 1.9258x; 1.1065x over previous
#include <cuda_runtime.h>
#include <cuda_bf16.h>
#include <cstdint>

// ProcessorNet reduction (exact up to fp reassociation):
//   z_0 = x@wd.T + bd ; m_t = relu(z_t + t*c)*prog_t ; R += m_t ; z += m_t@A
//   out = x + R@wu.T + 64*bu     (A = wu.T@wd.T, c = bu@wd.T)
// Phase B on tensor cores (mma.sync.m16n8k16 bf16):
//   z, R resident as D-fragments; A resident as B-fragments (hi+lo split);
//   R accumulated via identity-B MMAs; "+c" reconstructed as t*c in regs.
//   z += mh@Ah + mh@Al ; R += mh@I   (mh = bf16(m), err ~1e-5 overall)
// This round: 3 blocks/SM (reg diet to 84) to fix latency-bound issue=36%.

#define HDIM 128
#define LSTEPS 64

struct Consts {
    float A[16][16];           // A[j][i]
    float wd2[128][16];        // wd2[h][i] = wd[i][h]
    float prog[LSTEPS][16];
    float wupc[64][16][2];     // {wu[2hp][j], wu[2hp+1][j]}
    float bd[16];
    float c[16];               // bu @ wd.T
    float bu64[128];           // 64*bu
};
__device__ Consts g_c;

#define REGION0_FLOATS 8448    // tile 256*33 | z_s/R_s 256*18
#define PERSIST_FLOATS 5536
#define SMEM_FLOATS (REGION0_FLOATS + PERSIST_FLOATS)
#define SMEM_BYTES (SMEM_FLOATS * 4)   // 55936 ; x3 blocks = 167.8KB/SM

__global__ void setup_kernel(const float* __restrict__ prog,
                             const float* __restrict__ wd,
                             const float* __restrict__ bd,
                             const float* __restrict__ wu,
                             const float* __restrict__ bu) {
    int tid = threadIdx.x;  // 256
    {   // A[j][i] = sum_h wu[h][j] * wd[i][h]
        int j = tid >> 4, i = tid & 15;
        float s = 0.f;
        #pragma unroll 8
        for (int h = 0; h < HDIM; ++h) s += wu[h * 16 + j] * wd[i * HDIM + h];
        g_c.A[j][i] = s;
    }
    if (tid < 16) {
        int i = tid;
        float s = 0.f;
        #pragma unroll 8
        for (int h = 0; h < HDIM; ++h) s += bu[h] * wd[i * HDIM + h];
        g_c.c[i] = s;
        g_c.bd[i] = bd[i];
    }
    for (int idx = tid; idx < LSTEPS * 16; idx += 256)
        g_c.prog[idx >> 4][idx & 15] = prog[idx];
    for (int idx = tid; idx < 128 * 16; idx += 256) {
        int h = idx >> 4, i = idx & 15;
        g_c.wd2[h][i] = wd[i * HDIM + h];
    }
    for (int idx = tid; idx < 64 * 16; idx += 256) {
        int hp = idx >> 4, j = idx & 15;
        g_c.wupc[hp][j][0] = wu[(2 * hp) * 16 + j];
        g_c.wupc[hp][j][1] = wu[(2 * hp + 1) * 16 + j];
    }
    for (int idx = tid; idx < 128; idx += 256) g_c.bu64[idx] = 64.f * bu[idx];
}

// ---- helpers ----
typedef unsigned long long u64;
__device__ __forceinline__ u64 pk(float x, float y) {
    u64 r; asm("mov.b64 %0, {%1, %2};" : "=l"(r) : "f"(x), "f"(y)); return r;
}
__device__ __forceinline__ void upk(u64 v, float& x, float& y) {
    asm("mov.b64 {%0, %1}, %2;" : "=f"(x), "=f"(y) : "l"(v));
}
__device__ __forceinline__ u64 fma2(u64 a, u64 b, u64 c) {
    u64 d; asm("fma.rn.f32x2 %0, %1, %2, %3;" : "=l"(d) : "l"(a), "l"(b), "l"(c)); return d;
}
__device__ __forceinline__ uint32_t pkbf(float a, float b) {   // low=a, high=b
    __nv_bfloat162 h = __floats2bfloat162_rn(a, b);
    return *reinterpret_cast<uint32_t*>(&h);
}
__device__ __forceinline__ void mma_bf16(float* d, const uint32_t* a,
                                         const uint32_t* b) {
    asm volatile(
        "mma.sync.aligned.m16n8k16.row.col.f32.bf16.bf16.f32 "
        "{%0,%1,%2,%3}, {%4,%5,%6,%7}, {%8,%9}, {%0,%1,%2,%3};\n"
        : "+f"(d[0]), "+f"(d[1]), "+f"(d[2]), "+f"(d[3])
        : "r"(a[0]), "r"(a[1]), "r"(a[2]), "r"(a[3]), "r"(b[0]), "r"(b[1]));
}

__global__ __launch_bounds__(256, 3)
void proc_kernel(const float* __restrict__ x, float* __restrict__ out) {
    extern __shared__ float sm[];
    float* region0 = sm;                 // tile (A/C) | z_s/R_s (stride 18)
    float* s_A    = sm + REGION0_FLOATS; // 256
    float* s_wd2  = s_A + 256;           // 2048
    float* s_prog = s_wd2 + 2048;        // 1024
    float* s_wupc = s_prog + 1024;       // 2048
    float* s_bd   = s_wupc + 2048;       // 16
    float* s_c    = s_bd + 16;           // 16
    float* s_bu   = s_c + 16;            // 128

    int tid = threadIdx.x;
    {
        const float4* src = (const float4*)&g_c.A[0][0];
        float4* dst = (float4*)s_A;
        for (int i = tid; i < PERSIST_FLOATS / 4; i += 256) dst[i] = src[i];
    }
    __syncthreads();

    long row0 = (long)blockIdx.x * 256;
    const float* xr = x + row0 * HDIM;
    float* outr = out + row0 * HDIM;

    // ---- phase A: z = x@wd.T + bd (1 row/thread, f32x2) ----
    u64 z2[8];
    #pragma unroll
    for (int k = 0; k < 8; ++k) z2[k] = *(const u64*)(s_bd + 2 * k);
    for (int ch = 0; ch < 4; ++ch) {
        __syncthreads();
        for (int f = tid; f < 8192; f += 256) {
            int r = f >> 5, c = f & 31;
            region0[r * 33 + c] = xr[(long)r * HDIM + ch * 32 + c];
        }
        __syncthreads();
        #pragma unroll
        for (int c = 0; c < 32; ++c) {
            float xv = region0[tid * 33 + c];
            u64 xs = pk(xv, xv);
            const ulonglong2* w = (const ulonglong2*)(s_wd2 + (ch * 32 + c) * 16);
            #pragma unroll
            for (int kk = 0; kk < 4; ++kk) {
                ulonglong2 wv = w[kk];
                z2[2 * kk]     = fma2(xs, wv.x, z2[2 * kk]);
                z2[2 * kk + 1] = fma2(xs, wv.y, z2[2 * kk + 1]);
            }
        }
    }

    // ---- stage z into z_s[row][col], stride 18 ----
    __syncthreads();
    #pragma unroll
    for (int k = 0; k < 8; ++k) {
        float a, b; upk(z2[k], a, b);
        *(float2*)&region0[tid * 18 + 2 * k] = make_float2(a, b);
    }
    __syncwarp();

    // ---- fragment setup ----
    int lane = tid & 31, wrp = tid >> 5;
    int g = lane >> 2, tg = lane & 3;
    int rb = wrp * 32;
    int cbl = 2 * tg;

    // z/R fragments: d0:(g,cbl) d1:(g,cbl+1) d2:(g+8,cbl) d3:(g+8,cbl+1)
    float zf[2][2][4], Rf[2][2][4];
    #pragma unroll
    for (int tl = 0; tl < 2; ++tl) {
        int r0 = rb + tl * 16 + g, r1 = r0 + 8;
        #pragma unroll
        for (int cf = 0; cf < 2; ++cf) {
            int cb = cf * 8 + cbl;
            float2 lo = *(const float2*)&region0[r0 * 18 + cb];
            float2 hi = *(const float2*)&region0[r1 * 18 + cb];
            zf[tl][cf][0] = lo.x; zf[tl][cf][1] = lo.y;
            zf[tl][cf][2] = hi.x; zf[tl][cf][3] = hi.y;
            Rf[tl][cf][0] = Rf[tl][cf][1] = Rf[tl][cf][2] = Rf[tl][cf][3] = 0.f;
        }
    }

    // B fragments of A (col-major): b0={B[k0][n],B[k0+1][n]}, b1={B[k0+8][n],...}
    uint32_t bh[2][2], bl[2][2], bI[2][2];
    {
        int k0 = cbl;
        #pragma unroll
        for (int nc = 0; nc < 2; ++nc) {
            int n = g + nc * 8;
            float a0 = s_A[k0 * 16 + n],       a1 = s_A[(k0 + 1) * 16 + n];
            float a8 = s_A[(k0 + 8) * 16 + n], a9 = s_A[(k0 + 9) * 16 + n];
            uint32_t h0 = pkbf(a0, a1), h1 = pkbf(a8, a9);
            bh[nc][0] = h0; bh[nc][1] = h1;
            __nv_bfloat162 hb0 = *reinterpret_cast<__nv_bfloat162*>(&h0);
            __nv_bfloat162 hb1 = *reinterpret_cast<__nv_bfloat162*>(&h1);
            bl[nc][0] = pkbf(a0 - __low2float(hb0), a1 - __high2float(hb0));
            bl[nc][1] = pkbf(a8 - __low2float(hb1), a9 - __high2float(hb1));
            int j = nc * 8 + g;
            bI[nc][0] = pkbf((k0 == j) ? 1.f : 0.f, (k0 + 1 == j) ? 1.f : 0.f);
            bI[nc][1] = pkbf((k0 + 8 == j) ? 1.f : 0.f, (k0 + 9 == j) ? 1.f : 0.f);
        }
    }

    float cc[2][2] = {{s_c[cbl], s_c[cbl + 1]}, {s_c[8 + cbl], s_c[8 + cbl + 1]}};

    // ---- phase B: 64 steps; z += mh@Ah + mh@Al ; R += mh@I ----
    #pragma unroll 1
    for (int t = 0; t < LSTEPS; ++t) {
        float tf = (float)t;
        float zc0 = cc[0][0] * tf, zc1 = cc[0][1] * tf;
        float zc2 = cc[1][0] * tf, zc3 = cc[1][1] * tf;
        float2 pa = *(const float2*)&s_prog[t * 16 + cbl];
        float2 pb = *(const float2*)&s_prog[t * 16 + 8 + cbl];

        #pragma unroll
        for (int tl = 0; tl < 2; ++tl) {
            float m00 = fmaxf(zf[tl][0][0] + zc0, 0.f) * pa.x;
            float m01 = fmaxf(zf[tl][0][1] + zc1, 0.f) * pa.y;
            float m02 = fmaxf(zf[tl][0][2] + zc0, 0.f) * pa.x;
            float m03 = fmaxf(zf[tl][0][3] + zc1, 0.f) * pa.y;
            float m10 = fmaxf(zf[tl][1][0] + zc2, 0.f) * pb.x;
            float m11 = fmaxf(zf[tl][1][1] + zc3, 0.f) * pb.y;
            float m12 = fmaxf(zf[tl][1][2] + zc2, 0.f) * pb.x;
            float m13 = fmaxf(zf[tl][1][3] + zc3, 0.f) * pb.y;
            uint32_t ah[4];
            ah[0] = pkbf(m00, m01);
            ah[1] = pkbf(m02, m03);
            ah[2] = pkbf(m10, m11);
            ah[3] = pkbf(m12, m13);
            mma_bf16(zf[tl][0], ah, bh[0]);
            mma_bf16(zf[tl][1], ah, bh[1]);
            mma_bf16(Rf[tl][0], ah, bI[0]);
            mma_bf16(Rf[tl][1], ah, bI[1]);
            mma_bf16(zf[tl][0], ah, bl[0]);
            mma_bf16(zf[tl][1], ah, bl[1]);
        }
    }

    // ---- stage R back to R_s (warp-local mapping) ----
    #pragma unroll
    for (int tl = 0; tl < 2; ++tl) {
        int r0 = rb + tl * 16 + g, r1 = r0 + 8;
        #pragma unroll
        for (int cf = 0; cf < 2; ++cf) {
            int cb = cf * 8 + cbl;
            *(float2*)&region0[r0 * 18 + cb] = make_float2(Rf[tl][cf][0], Rf[tl][cf][1]);
            *(float2*)&region0[r1 * 18 + cb] = make_float2(Rf[tl][cf][2], Rf[tl][cf][3]);
        }
    }
    __syncwarp();

    u64 Rs[16];
    #pragma unroll
    for (int k = 0; k < 8; ++k) {
        float2 v = *(const float2*)&region0[tid * 18 + 2 * k];
        Rs[2 * k]     = pk(v.x, v.x);
        Rs[2 * k + 1] = pk(v.y, v.y);
    }

    // ---- phase C: out = x + R@wu.T + 64*bu ----
    for (int ch = 0; ch < 4; ++ch) {
        __syncthreads();
        #pragma unroll
        for (int hp = 0; hp < 16; ++hp) {
            int h2 = ch * 16 + hp;
            u64 acc = *(const u64*)(s_bu + h2 * 2);
            const ulonglong2* urow = (const ulonglong2*)(s_wupc + h2 * 32);
            #pragma unroll
            for (int jj = 0; jj < 8; ++jj) {
                ulonglong2 u = urow[jj];
                acc = fma2(Rs[2 * jj],     u.x, acc);
                acc = fma2(Rs[2 * jj + 1], u.y, acc);
            }
            float y0, y1;
            upk(acc, y0, y1);
            region0[tid * 33 + 2 * hp]     = y0;
            region0[tid * 33 + 2 * hp + 1] = y1;
        }
        __syncthreads();
        for (int f = tid; f < 8192; f += 256) {
            int r = f >> 5, c = f & 31;
            long gg = (long)r * HDIM + ch * 32 + c;
            outr[gg] = xr[gg] + region0[r * 33 + c];
        }
    }
}

extern "C" void kernel_launch(void* const* d_in, const int* in_sizes, int n_in,
                              void* d_out, int out_size) {
    const float* x    = (const float*)d_in[0];
    const float* prog = (const float*)d_in[1];
    const float* wd   = (const float*)d_in[2];
    const float* bd   = (const float*)d_in[3];
    const float* wu   = (const float*)d_in[4];
    const float* bu   = (const float*)d_in[5];
    float* out = (float*)d_out;

    cudaFuncSetAttribute(proc_kernel,
                         cudaFuncAttributeMaxDynamicSharedMemorySize, SMEM_BYTES);

    setup_kernel<<<1, 256>>>(prog, wd, bd, wu, bu);

    int rows = in_sizes[0] / HDIM;          // 262144
    int blocks = rows / 256;                // 1024
    proc_kernel<<<blocks, 256, SMEM_BYTES>>>(x, out);
}

// round 13
// speedup vs baseline: 2.1104x; 1.0958x over previous
#include <cuda_runtime.h>
#include <cuda_bf16.h>
#include <cstdint>

// ProcessorNet reduction (exact up to fp reassociation):
//   z_0 = x@wd.T + bd ; m_t = relu(z_t + t*c)*prog_t ; R += m_t ; z += m_t@A
//   out = x + R@wu.T + 64*bu     (A = wu.T@wd.T, c = bu@wd.T)
// Phase B on tensor cores (mma.sync.m16n8k16 bf16):
//   z, R resident as D-fragments; A resident as B-fragments (bf16-hi);
//   R accumulated via identity-B MMAs; "+c" reconstructed as t*c in regs.
//   z += mh@Ah ; R += mh@I   (err ~3e-5 total, 30x under tolerance)
// This round: drop Al compensation (8 MMAs/step), 4 blocks/SM (64-reg cap).

#define HDIM 128
#define LSTEPS 64

struct Consts {
    float A[16][16];           // A[j][i]
    float wd2[128][16];        // wd2[h][i] = wd[i][h]
    float prog[LSTEPS][16];
    float wupc[64][16][2];     // {wu[2hp][j], wu[2hp+1][j]}
    float bd[16];
    float c[16];               // bu @ wd.T
    float bu64[128];           // 64*bu
};
__device__ Consts g_c;

#define REGION0_FLOATS 8448    // tile 256*33 | z_s/R_s 256*18
#define PERSIST_FLOATS 5536
#define SMEM_FLOATS (REGION0_FLOATS + PERSIST_FLOATS)
#define SMEM_BYTES (SMEM_FLOATS * 4)   // 55936 ; x4 blocks = 218.5KiB/SM

__global__ void setup_kernel(const float* __restrict__ prog,
                             const float* __restrict__ wd,
                             const float* __restrict__ bd,
                             const float* __restrict__ wu,
                             const float* __restrict__ bu) {
    int tid = threadIdx.x;  // 256
    {   // A[j][i] = sum_h wu[h][j] * wd[i][h]
        int j = tid >> 4, i = tid & 15;
        float s = 0.f;
        #pragma unroll 8
        for (int h = 0; h < HDIM; ++h) s += wu[h * 16 + j] * wd[i * HDIM + h];
        g_c.A[j][i] = s;
    }
    if (tid < 16) {
        int i = tid;
        float s = 0.f;
        #pragma unroll 8
        for (int h = 0; h < HDIM; ++h) s += bu[h] * wd[i * HDIM + h];
        g_c.c[i] = s;
        g_c.bd[i] = bd[i];
    }
    for (int idx = tid; idx < LSTEPS * 16; idx += 256)
        g_c.prog[idx >> 4][idx & 15] = prog[idx];
    for (int idx = tid; idx < 128 * 16; idx += 256) {
        int h = idx >> 4, i = idx & 15;
        g_c.wd2[h][i] = wd[i * HDIM + h];
    }
    for (int idx = tid; idx < 64 * 16; idx += 256) {
        int hp = idx >> 4, j = idx & 15;
        g_c.wupc[hp][j][0] = wu[(2 * hp) * 16 + j];
        g_c.wupc[hp][j][1] = wu[(2 * hp + 1) * 16 + j];
    }
    for (int idx = tid; idx < 128; idx += 256) g_c.bu64[idx] = 64.f * bu[idx];
}

// ---- helpers ----
typedef unsigned long long u64;
__device__ __forceinline__ u64 pk(float x, float y) {
    u64 r; asm("mov.b64 %0, {%1, %2};" : "=l"(r) : "f"(x), "f"(y)); return r;
}
__device__ __forceinline__ void upk(u64 v, float& x, float& y) {
    asm("mov.b64 {%0, %1}, %2;" : "=f"(x), "=f"(y) : "l"(v));
}
__device__ __forceinline__ u64 fma2(u64 a, u64 b, u64 c) {
    u64 d; asm("fma.rn.f32x2 %0, %1, %2, %3;" : "=l"(d) : "l"(a), "l"(b), "l"(c)); return d;
}
__device__ __forceinline__ uint32_t pkbf(float a, float b) {   // low=a, high=b
    __nv_bfloat162 h = __floats2bfloat162_rn(a, b);
    return *reinterpret_cast<uint32_t*>(&h);
}
__device__ __forceinline__ void mma_bf16(float* d, const uint32_t* a,
                                         const uint32_t* b) {
    asm volatile(
        "mma.sync.aligned.m16n8k16.row.col.f32.bf16.bf16.f32 "
        "{%0,%1,%2,%3}, {%4,%5,%6,%7}, {%8,%9}, {%0,%1,%2,%3};\n"
        : "+f"(d[0]), "+f"(d[1]), "+f"(d[2]), "+f"(d[3])
        : "r"(a[0]), "r"(a[1]), "r"(a[2]), "r"(a[3]), "r"(b[0]), "r"(b[1]));
}

__global__ __launch_bounds__(256, 4)
void proc_kernel(const float* __restrict__ x, float* __restrict__ out) {
    extern __shared__ float sm[];
    float* region0 = sm;                 // tile (A/C) | z_s/R_s (stride 18)
    float* s_A    = sm + REGION0_FLOATS; // 256
    float* s_wd2  = s_A + 256;           // 2048
    float* s_prog = s_wd2 + 2048;        // 1024
    float* s_wupc = s_prog + 1024;       // 2048
    float* s_bd   = s_wupc + 2048;       // 16
    float* s_c    = s_bd + 16;           // 16
    float* s_bu   = s_c + 16;            // 128

    int tid = threadIdx.x;
    {
        const float4* src = (const float4*)&g_c.A[0][0];
        float4* dst = (float4*)s_A;
        for (int i = tid; i < PERSIST_FLOATS / 4; i += 256) dst[i] = src[i];
    }
    __syncthreads();

    long row0 = (long)blockIdx.x * 256;
    const float* xr = x + row0 * HDIM;
    float* outr = out + row0 * HDIM;

    // ---- phase A: z = x@wd.T + bd (1 row/thread, f32x2) ----
    u64 z2[8];
    #pragma unroll
    for (int k = 0; k < 8; ++k) z2[k] = *(const u64*)(s_bd + 2 * k);
    for (int ch = 0; ch < 4; ++ch) {
        __syncthreads();
        for (int f = tid; f < 8192; f += 256) {
            int r = f >> 5, c = f & 31;
            region0[r * 33 + c] = xr[(long)r * HDIM + ch * 32 + c];
        }
        __syncthreads();
        #pragma unroll
        for (int c = 0; c < 32; ++c) {
            float xv = region0[tid * 33 + c];
            u64 xs = pk(xv, xv);
            const ulonglong2* w = (const ulonglong2*)(s_wd2 + (ch * 32 + c) * 16);
            #pragma unroll
            for (int kk = 0; kk < 4; ++kk) {
                ulonglong2 wv = w[kk];
                z2[2 * kk]     = fma2(xs, wv.x, z2[2 * kk]);
                z2[2 * kk + 1] = fma2(xs, wv.y, z2[2 * kk + 1]);
            }
        }
    }

    // ---- stage z into z_s[row][col], stride 18 ----
    __syncthreads();
    #pragma unroll
    for (int k = 0; k < 8; ++k) {
        float a, b; upk(z2[k], a, b);
        *(float2*)&region0[tid * 18 + 2 * k] = make_float2(a, b);
    }
    __syncwarp();

    // ---- fragment setup ----
    int lane = tid & 31, wrp = tid >> 5;
    int g = lane >> 2, tg = lane & 3;
    int rb = wrp * 32;
    int cbl = 2 * tg;

    // z/R fragments: d0:(g,cbl) d1:(g,cbl+1) d2:(g+8,cbl) d3:(g+8,cbl+1)
    float zf[2][2][4], Rf[2][2][4];
    #pragma unroll
    for (int tl = 0; tl < 2; ++tl) {
        int r0 = rb + tl * 16 + g, r1 = r0 + 8;
        #pragma unroll
        for (int cf = 0; cf < 2; ++cf) {
            int cb = cf * 8 + cbl;
            float2 lo = *(const float2*)&region0[r0 * 18 + cb];
            float2 hi = *(const float2*)&region0[r1 * 18 + cb];
            zf[tl][cf][0] = lo.x; zf[tl][cf][1] = lo.y;
            zf[tl][cf][2] = hi.x; zf[tl][cf][3] = hi.y;
            Rf[tl][cf][0] = Rf[tl][cf][1] = Rf[tl][cf][2] = Rf[tl][cf][3] = 0.f;
        }
    }

    // B fragments of A (col-major): b0={B[k0][n],B[k0+1][n]}, b1={B[k0+8][n],...}
    uint32_t bh[2][2], bI[2][2];
    {
        int k0 = cbl;
        #pragma unroll
        for (int nc = 0; nc < 2; ++nc) {
            int n = g + nc * 8;
            bh[nc][0] = pkbf(s_A[k0 * 16 + n],       s_A[(k0 + 1) * 16 + n]);
            bh[nc][1] = pkbf(s_A[(k0 + 8) * 16 + n], s_A[(k0 + 9) * 16 + n]);
            int j = nc * 8 + g;
            bI[nc][0] = pkbf((k0 == j) ? 1.f : 0.f, (k0 + 1 == j) ? 1.f : 0.f);
            bI[nc][1] = pkbf((k0 + 8 == j) ? 1.f : 0.f, (k0 + 9 == j) ? 1.f : 0.f);
        }
    }

    float cc[2][2] = {{s_c[cbl], s_c[cbl + 1]}, {s_c[8 + cbl], s_c[8 + cbl + 1]}};

    // ---- phase B: 64 steps; z += mh@Ah ; R += mh@I ----
    #pragma unroll 1
    for (int t = 0; t < LSTEPS; ++t) {
        float tf = (float)t;
        float zc0 = cc[0][0] * tf, zc1 = cc[0][1] * tf;
        float zc2 = cc[1][0] * tf, zc3 = cc[1][1] * tf;
        float2 pa = *(const float2*)&s_prog[t * 16 + cbl];
        float2 pb = *(const float2*)&s_prog[t * 16 + 8 + cbl];

        #pragma unroll
        for (int tl = 0; tl < 2; ++tl) {
            float m00 = fmaxf(zf[tl][0][0] + zc0, 0.f) * pa.x;
            float m01 = fmaxf(zf[tl][0][1] + zc1, 0.f) * pa.y;
            float m02 = fmaxf(zf[tl][0][2] + zc0, 0.f) * pa.x;
            float m03 = fmaxf(zf[tl][0][3] + zc1, 0.f) * pa.y;
            float m10 = fmaxf(zf[tl][1][0] + zc2, 0.f) * pb.x;
            float m11 = fmaxf(zf[tl][1][1] + zc3, 0.f) * pb.y;
            float m12 = fmaxf(zf[tl][1][2] + zc2, 0.f) * pb.x;
            float m13 = fmaxf(zf[tl][1][3] + zc3, 0.f) * pb.y;
            uint32_t ah[4];
            ah[0] = pkbf(m00, m01);
            ah[1] = pkbf(m02, m03);
            ah[2] = pkbf(m10, m11);
            ah[3] = pkbf(m12, m13);
            mma_bf16(zf[tl][0], ah, bh[0]);
            mma_bf16(zf[tl][1], ah, bh[1]);
            mma_bf16(Rf[tl][0], ah, bI[0]);
            mma_bf16(Rf[tl][1], ah, bI[1]);
        }
    }

    // ---- stage R back to R_s (warp-local mapping) ----
    #pragma unroll
    for (int tl = 0; tl < 2; ++tl) {
        int r0 = rb + tl * 16 + g, r1 = r0 + 8;
        #pragma unroll
        for (int cf = 0; cf < 2; ++cf) {
            int cb = cf * 8 + cbl;
            *(float2*)&region0[r0 * 18 + cb] = make_float2(Rf[tl][cf][0], Rf[tl][cf][1]);
            *(float2*)&region0[r1 * 18 + cb] = make_float2(Rf[tl][cf][2], Rf[tl][cf][3]);
        }
    }
    __syncwarp();

    u64 Rs[16];
    #pragma unroll
    for (int k = 0; k < 8; ++k) {
        float2 v = *(const float2*)&region0[tid * 18 + 2 * k];
        Rs[2 * k]     = pk(v.x, v.x);
        Rs[2 * k + 1] = pk(v.y, v.y);
    }

    // ---- phase C: out = x + R@wu.T + 64*bu ----
    for (int ch = 0; ch < 4; ++ch) {
        __syncthreads();
        #pragma unroll
        for (int hp = 0; hp < 16; ++hp) {
            int h2 = ch * 16 + hp;
            u64 acc = *(const u64*)(s_bu + h2 * 2);
            const ulonglong2* urow = (const ulonglong2*)(s_wupc + h2 * 32);
            #pragma unroll
            for (int jj = 0; jj < 8; ++jj) {
                ulonglong2 u = urow[jj];
                acc = fma2(Rs[2 * jj],     u.x, acc);
                acc = fma2(Rs[2 * jj + 1], u.y, acc);
            }
            float y0, y1;
            upk(acc, y0, y1);
            region0[tid * 33 + 2 * hp]     = y0;
            region0[tid * 33 + 2 * hp + 1] = y1;
        }
        __syncthreads();
        for (int f = tid; f < 8192; f += 256) {
            int r = f >> 5, c = f & 31;
            long gg = (long)r * HDIM + ch * 32 + c;
            outr[gg] = xr[gg] + region0[r * 33 + c];
        }
    }
}

extern "C" void kernel_launch(void* const* d_in, const int* in_sizes, int n_in,
                              void* d_out, int out_size) {
    const float* x    = (const float*)d_in[0];
    const float* prog = (const float*)d_in[1];
    const float* wd   = (const float*)d_in[2];
    const float* bd   = (const float*)d_in[3];
    const float* wu   = (const float*)d_in[4];
    const float* bu   = (const float*)d_in[5];
    float* out = (float*)d_out;

    cudaFuncSetAttribute(proc_kernel,
                         cudaFuncAttributeMaxDynamicSharedMemorySize, SMEM_BYTES);

    setup_kernel<<<1, 256>>>(prog, wd, bd, wu, bu);

    int rows = in_sizes[0] / HDIM;          // 262144
    int blocks = rows / 256;                // 1024
    proc_kernel<<<blocks, 256, SMEM_BYTES>>>(x, out);
}

// round 14
// speedup vs baseline: 3.3856x; 1.6043x over previous
#include <cuda_runtime.h>
#include <cuda_bf16.h>
#include <cstdint>

// ProcessorNet, fully tensor-core resident:
//   z_0 = x@wd.T + bd            (MMA: x hi/lo from gmem, wd B-frags from smem)
//   m_t = relu(z_t + t*c)*prog_t ; R += m_t (I-MMA) ; z += m_t@A (MMA, A-hi)
//   out = x + R@wu.T + 64*bu     (MMA: R hi/lo, wu B-frags; D init = x+64bu)
// z, R live as D-fragments the whole time. No smem tiles, no broadcast LDS.

#define HDIM 128
#define LSTEPS 64

struct Consts {
    float A[16][16];            // A[j][i] = (wu.T@wd.T)[j][i]
    float prog[LSTEPS][16];
    float bd[16];
    float c[16];                // bu @ wd.T
    float bu64[128];            // 64*bu
    unsigned long long wdf[8][2][2][32];  // [kc][cf][hi/lo][lane] B-frags of wd
    unsigned long long wuf[16][2][32];    // [cfc][hi/lo][lane]   B-frags of wu
};
__device__ Consts g_c;
#define CONST_FLOATS (sizeof(Consts) / 4)   // 5536

__device__ __forceinline__ float bhi_f(float v) {
    return __bfloat162float(__float2bfloat16(v));
}

__global__ void setup_kernel(const float* __restrict__ prog,
                             const float* __restrict__ wd,
                             const float* __restrict__ bd,
                             const float* __restrict__ wu,
                             const float* __restrict__ bu) {
    int tid = threadIdx.x;  // 256
    {   // A[j][i] = sum_h wu[h][j] * wd[i][h]
        int j = tid >> 4, i = tid & 15;
        float s = 0.f;
        #pragma unroll 8
        for (int h = 0; h < HDIM; ++h) s += wu[h * 16 + j] * wd[i * HDIM + h];
        g_c.A[j][i] = s;
    }
    if (tid < 16) {
        int i = tid;
        float s = 0.f;
        #pragma unroll 8
        for (int h = 0; h < HDIM; ++h) s += bu[h] * wd[i * HDIM + h];
        g_c.c[i] = s;
        g_c.bd[i] = bd[i];
    }
    for (int idx = tid; idx < LSTEPS * 16; idx += 256)
        g_c.prog[idx >> 4][idx & 15] = prog[idx];
    for (int idx = tid; idx < 128; idx += 256) g_c.bu64[idx] = 64.f * bu[idx];

    // wd B-fragments: B[k][n] = wd[i][k], i = cf*8+g, k0 = kc*16 + 2*tg
    for (int idx = tid; idx < 1024; idx += 256) {
        int kc = idx >> 7, cf = (idx >> 6) & 1, hl = (idx >> 5) & 1, lane = idx & 31;
        int g = lane >> 2, tg = lane & 3;
        int i = cf * 8 + g;
        int k0 = kc * 16 + 2 * tg;
        float v0 = wd[i * HDIM + k0],     v1 = wd[i * HDIM + k0 + 1];
        float v2 = wd[i * HDIM + k0 + 8], v3 = wd[i * HDIM + k0 + 9];
        if (hl) { v0 -= bhi_f(v0); v1 -= bhi_f(v1); v2 -= bhi_f(v2); v3 -= bhi_f(v3); }
        __nv_bfloat162 r0 = __floats2bfloat162_rn(v0, v1);
        __nv_bfloat162 r1 = __floats2bfloat162_rn(v2, v3);
        unsigned long long u = ((unsigned long long)*(uint32_t*)&r1 << 32)
                             | *(uint32_t*)&r0;
        g_c.wdf[kc][cf][hl][lane] = u;
    }
    // wu B-fragments: B[j][n] = wu[h][j], h = cfc*8+g, j0 = 2*tg
    for (int idx = tid; idx < 1024; idx += 256) {
        int cfc = idx >> 6, hl = (idx >> 5) & 1, lane = idx & 31;
        int g = lane >> 2, tg = lane & 3;
        int h = cfc * 8 + g;
        int j0 = 2 * tg;
        float v0 = wu[h * 16 + j0],     v1 = wu[h * 16 + j0 + 1];
        float v2 = wu[h * 16 + j0 + 8], v3 = wu[h * 16 + j0 + 9];
        if (hl) { v0 -= bhi_f(v0); v1 -= bhi_f(v1); v2 -= bhi_f(v2); v3 -= bhi_f(v3); }
        __nv_bfloat162 r0 = __floats2bfloat162_rn(v0, v1);
        __nv_bfloat162 r1 = __floats2bfloat162_rn(v2, v3);
        unsigned long long u = ((unsigned long long)*(uint32_t*)&r1 << 32)
                             | *(uint32_t*)&r0;
        g_c.wuf[cfc][hl][lane] = u;
    }
}

// ---- helpers ----
__device__ __forceinline__ uint32_t pkbf(float a, float b) {   // low=a, high=b
    __nv_bfloat162 h = __floats2bfloat162_rn(a, b);
    return *reinterpret_cast<uint32_t*>(&h);
}
__device__ __forceinline__ void mma_bf16(float* d, const uint32_t* a,
                                         const uint32_t* b) {
    asm volatile(
        "mma.sync.aligned.m16n8k16.row.col.f32.bf16.bf16.f32 "
        "{%0,%1,%2,%3}, {%4,%5,%6,%7}, {%8,%9}, {%0,%1,%2,%3};\n"
        : "+f"(d[0]), "+f"(d[1]), "+f"(d[2]), "+f"(d[3])
        : "r"(a[0]), "r"(a[1]), "r"(a[2]), "r"(a[3]), "r"(b[0]), "r"(b[1]));
}
__device__ __forceinline__ void split_u64(unsigned long long v, uint32_t* b) {
    b[0] = (uint32_t)v; b[1] = (uint32_t)(v >> 32);
}

__global__ __launch_bounds__(256, 4)
void proc_kernel(const float* __restrict__ x, float* __restrict__ out) {
    __shared__ Consts sc;
    int tid = threadIdx.x;
    {
        const float4* src = (const float4*)&g_c;
        float4* dst = (float4*)&sc;
        for (int i = tid; i < CONST_FLOATS / 4; i += 256) dst[i] = src[i];
    }
    __syncthreads();

    int lane = tid & 31, wrp = tid >> 5;
    int g = lane >> 2, tg = lane & 3;
    int cbl = 2 * tg;

    long row0 = (long)blockIdx.x * 256 + wrp * 32;   // this warp's 32 rows
    const float* xw = x + row0 * HDIM;
    float* ow = out + row0 * HDIM;

    // ---- phase A: zf = bd ; zf += x@wd.T  (MMA, x hi/lo direct from gmem) ----
    float zf[2][2][4], Rf[2][2][4];
    #pragma unroll
    for (int tl = 0; tl < 2; ++tl)
        #pragma unroll
        for (int cf = 0; cf < 2; ++cf) {
            float b0 = sc.bd[cf * 8 + cbl], b1 = sc.bd[cf * 8 + cbl + 1];
            zf[tl][cf][0] = b0; zf[tl][cf][1] = b1;
            zf[tl][cf][2] = b0; zf[tl][cf][3] = b1;
            Rf[tl][cf][0] = Rf[tl][cf][1] = Rf[tl][cf][2] = Rf[tl][cf][3] = 0.f;
        }

    #pragma unroll 1
    for (int kc = 0; kc < 8; ++kc) {
        uint32_t wh0[2], wl0[2], wh1[2], wl1[2];
        split_u64(sc.wdf[kc][0][0][lane], wh0);
        split_u64(sc.wdf[kc][0][1][lane], wl0);
        split_u64(sc.wdf[kc][1][0][lane], wh1);
        split_u64(sc.wdf[kc][1][1][lane], wl1);
        #pragma unroll
        for (int tl = 0; tl < 2; ++tl) {
            const float* xp = xw + (long)(tl * 16 + g) * HDIM + kc * 16 + cbl;
            float2 v0 = *(const float2*)xp;
            float2 v1 = *(const float2*)(xp + 8 * HDIM);
            float2 v2 = *(const float2*)(xp + 8);
            float2 v3 = *(const float2*)(xp + 8 * HDIM + 8);
            uint32_t ah[4], al[4];
            ah[0] = pkbf(v0.x, v0.y); ah[1] = pkbf(v1.x, v1.y);
            ah[2] = pkbf(v2.x, v2.y); ah[3] = pkbf(v3.x, v3.y);
            al[0] = pkbf(v0.x - bhi_f(v0.x), v0.y - bhi_f(v0.y));
            al[1] = pkbf(v1.x - bhi_f(v1.x), v1.y - bhi_f(v1.y));
            al[2] = pkbf(v2.x - bhi_f(v2.x), v2.y - bhi_f(v2.y));
            al[3] = pkbf(v3.x - bhi_f(v3.x), v3.y - bhi_f(v3.y));
            mma_bf16(zf[tl][0], ah, wh0);
            mma_bf16(zf[tl][0], al, wh0);
            mma_bf16(zf[tl][0], ah, wl0);
            mma_bf16(zf[tl][1], ah, wh1);
            mma_bf16(zf[tl][1], al, wh1);
            mma_bf16(zf[tl][1], ah, wl1);
        }
    }

    // ---- phase B fragments of A (bf16-hi) + identity ----
    uint32_t bh[2][2], bI[2][2];
    {
        int k0 = cbl;
        #pragma unroll
        for (int nc = 0; nc < 2; ++nc) {
            int n = g + nc * 8;
            bh[nc][0] = pkbf(sc.A[k0][n],     sc.A[k0 + 1][n]);
            bh[nc][1] = pkbf(sc.A[k0 + 8][n], sc.A[k0 + 9][n]);
            int j = nc * 8 + g;
            bI[nc][0] = pkbf((k0 == j) ? 1.f : 0.f, (k0 + 1 == j) ? 1.f : 0.f);
            bI[nc][1] = pkbf((k0 + 8 == j) ? 1.f : 0.f, (k0 + 9 == j) ? 1.f : 0.f);
        }
    }
    float cc[2][2] = {{sc.c[cbl], sc.c[cbl + 1]},
                      {sc.c[8 + cbl], sc.c[8 + cbl + 1]}};

    // ---- phase B: 64 steps; z += mh@Ah ; R += mh@I ----
    #pragma unroll 1
    for (int t = 0; t < LSTEPS; ++t) {
        float tf = (float)t;
        float zc0 = cc[0][0] * tf, zc1 = cc[0][1] * tf;
        float zc2 = cc[1][0] * tf, zc3 = cc[1][1] * tf;
        float2 pa = *(const float2*)&sc.prog[t][cbl];
        float2 pb = *(const float2*)&sc.prog[t][8 + cbl];

        #pragma unroll
        for (int tl = 0; tl < 2; ++tl) {
            float m00 = fmaxf(zf[tl][0][0] + zc0, 0.f) * pa.x;
            float m01 = fmaxf(zf[tl][0][1] + zc1, 0.f) * pa.y;
            float m02 = fmaxf(zf[tl][0][2] + zc0, 0.f) * pa.x;
            float m03 = fmaxf(zf[tl][0][3] + zc1, 0.f) * pa.y;
            float m10 = fmaxf(zf[tl][1][0] + zc2, 0.f) * pb.x;
            float m11 = fmaxf(zf[tl][1][1] + zc3, 0.f) * pb.y;
            float m12 = fmaxf(zf[tl][1][2] + zc2, 0.f) * pb.x;
            float m13 = fmaxf(zf[tl][1][3] + zc3, 0.f) * pb.y;
            uint32_t ah[4];
            ah[0] = pkbf(m00, m01);
            ah[1] = pkbf(m02, m03);
            ah[2] = pkbf(m10, m11);
            ah[3] = pkbf(m12, m13);
            mma_bf16(zf[tl][0], ah, bh[0]);
            mma_bf16(zf[tl][1], ah, bh[1]);
            mma_bf16(Rf[tl][0], ah, bI[0]);
            mma_bf16(Rf[tl][1], ah, bI[1]);
        }
    }

    // ---- phase C: out = x + R@wu.T + 64*bu  (MMA, D init = x + bu64) ----
    #pragma unroll
    for (int tl = 0; tl < 2; ++tl) {
        uint32_t rh[4], rl[4];
        rh[0] = pkbf(Rf[tl][0][0], Rf[tl][0][1]);
        rh[1] = pkbf(Rf[tl][0][2], Rf[tl][0][3]);
        rh[2] = pkbf(Rf[tl][1][0], Rf[tl][1][1]);
        rh[3] = pkbf(Rf[tl][1][2], Rf[tl][1][3]);
        rl[0] = pkbf(Rf[tl][0][0] - bhi_f(Rf[tl][0][0]),
                     Rf[tl][0][1] - bhi_f(Rf[tl][0][1]));
        rl[1] = pkbf(Rf[tl][0][2] - bhi_f(Rf[tl][0][2]),
                     Rf[tl][0][3] - bhi_f(Rf[tl][0][3]));
        rl[2] = pkbf(Rf[tl][1][0] - bhi_f(Rf[tl][1][0]),
                     Rf[tl][1][1] - bhi_f(Rf[tl][1][1]));
        rl[3] = pkbf(Rf[tl][1][2] - bhi_f(Rf[tl][1][2]),
                     Rf[tl][1][3] - bhi_f(Rf[tl][1][3]));

        #pragma unroll 1
        for (int cfc = 0; cfc < 16; ++cfc) {
            int h0 = cfc * 8 + cbl;
            const float* xp0 = xw + (long)(tl * 16 + g) * HDIM + h0;
            const float* xp1 = xp0 + 8 * HDIM;
            float2 xv0 = *(const float2*)xp0;
            float2 xv1 = *(const float2*)xp1;
            float2 bu2 = *(const float2*)&sc.bu64[h0];
            float o[4] = {xv0.x + bu2.x, xv0.y + bu2.y,
                          xv1.x + bu2.x, xv1.y + bu2.y};
            uint32_t wh[2], wl[2];
            split_u64(sc.wuf[cfc][0][lane], wh);
            split_u64(sc.wuf[cfc][1][lane], wl);
            mma_bf16(o, rh, wh);
            mma_bf16(o, rl, wh);
            mma_bf16(o, rh, wl);
            float* op0 = ow + (long)(tl * 16 + g) * HDIM + h0;
            *(float2*)op0            = make_float2(o[0], o[1]);
            *(float2*)(op0 + 8 * HDIM) = make_float2(o[2], o[3]);
        }
    }
}

extern "C" void kernel_launch(void* const* d_in, const int* in_sizes, int n_in,
                              void* d_out, int out_size) {
    const float* x    = (const float*)d_in[0];
    const float* prog = (const float*)d_in[1];
    const float* wd   = (const float*)d_in[2];
    const float* bd   = (const float*)d_in[3];
    const float* wu   = (const float*)d_in[4];
    const float* bu   = (const float*)d_in[5];
    float* out = (float*)d_out;

    setup_kernel<<<1, 256>>>(prog, wd, bd, wu, bu);

    int rows = in_sizes[0] / HDIM;          // 262144
    int blocks = rows / 256;                // 1024
    proc_kernel<<<blocks, 256>>>(x, out);
}